// round 12
// baseline (speedup 1.0000x reference)
#include <cuda_runtime.h>
#include <math.h>

#define HWSZ 65536
#define NB 8
#define NPIX (NB * HWSZ)
#define CAND_T 0.40f
#define NZBLK 512                 // zero-fill blocks  (blockIdx [0,512))
#define NCBLK 512                 // compute blocks    (blockIdx [512,1024))
#define SEG 1024                  // candidate segment size per compute block

__device__ float g_seg_val[NCBLK * SEG];  // per-block candidate scores
__device__ float g_seg_wm[NCBLK * SEG];   // per-block candidate wmap values
__device__ int   g_seg_idx[NCBLK * SEG];  // per-block candidate pixel index
__device__ int   g_seg_cnt[NCBLK];
__device__ float g_part[NCBLK * 10];      // per-block sorted top-10 (all scores)
__device__ int   g_done[NB];              // batch completion tickets (self-reset)
__device__ int   g_zero_done;             // zero-fill completion    (self-reset)
__device__ int   g_tail_done;             // finalize-tail ticket    (self-reset)
__device__ float g_thresh[NB];            // exact 10th-largest score per batch

// ---------------------------------------------------------------------------
// Warp merge-pop: each lane holds a sorted (desc) D-list; 10 rounds of
// butterfly argmax over heads; winner pops. out10 (lane 0) gets sorted top-10.
// Returns the 10th value.
// ---------------------------------------------------------------------------
template <int D>
__device__ __forceinline__ float warp_merge_pop(float (&top)[D], int lane,
                                                float* out10) {
    float last = -INFINITY;
#pragma unroll
    for (int r = 0; r < 10; r++) {
        float v = top[0]; int vi = lane;
#pragma unroll
        for (int off = 16; off; off >>= 1) {
            float ov = __shfl_xor_sync(0xffffffffu, v, off);
            int   oi = __shfl_xor_sync(0xffffffffu, vi, off);
            if (ov > v || (ov == v && oi < vi)) { v = ov; vi = oi; }
        }
        if (lane == vi) {
#pragma unroll
            for (int k = 0; k < D - 1; k++) top[k] = top[k + 1];
            top[D - 1] = -INFINITY;
        }
        if (out10 && lane == 0) out10[r] = v;
        last = v;
    }
    return last;
}

// ---------------------------------------------------------------------------
// Single fused kernel.
// Blocks [0,512): zero-fill out_box|out_m, then raise g_zero_done.
// Blocks [512,1024): score + wmap (4 px/thread, streaming loads), candidate
// append, block top-10. Last block per batch: merge 64 lists -> t10, gate on
// zero-fill completion, then sparse finalize of the batch's 64 segments.
// All tickets self-reset for graph replay.
// ---------------------------------------------------------------------------
__global__ void __launch_bounds__(256, 3) k_main(
    const float* __restrict__ color, const float* __restrict__ w_bbx,
    const float* __restrict__ w_width, const float* __restrict__ w_score,
    float* __restrict__ score_out, float* __restrict__ out_box,
    float* __restrict__ out_m) {
    int t = threadIdx.x;
    if (blockIdx.x < NZBLK) {                // zero-fill path: 6144 floats/block
        float* p = out_box + (size_t)blockIdx.x * 6144 + t * 4;
        float4 z = make_float4(0.f, 0.f, 0.f, 0.f);
#pragma unroll
        for (int q = 0; q < 6; q++) *(float4*)(p + q * 1024) = z;
        __syncthreads();
        if (t == 0) { __threadfence(); atomicAdd(&g_zero_done, 1); }
        return;
    }

    __shared__ float ws[64];
    __shared__ float cwt[160];
    __shared__ float wtop[8 * 10];
    __shared__ float wlist[2][10];
    __shared__ float s_t10;
    __shared__ int   scnt;
    __shared__ int   s_last;
    if (t == 0) scnt = 0;
    if (t < 64) ws[t] = w_score[t];
    if (t < 160) cwt[t] = w_bbx[2 * (t / 5)] * w_width[t];
    __syncthreads();

    int cb = blockIdx.x - NZBLK;             // compute-block id [0,512)
    int p4 = (cb * 256 + t) * 4;
    int b  = p4 >> 16;
    int hw = p4 & (HWSZ - 1);
    int w0 = hw & 255;
    const float* base = color + ((size_t)b * 64) * HWSZ + hw;

    float4 s = make_float4(0.f, 0.f, 0.f, 0.f);
    float m0 = -INFINITY, m1 = -INFINITY, m2 = -INFINITY, m3 = -INFINITY;
    const bool hasL = (w0 != 0), hasR = (w0 != 252);

#pragma unroll 4
    for (int i = 0; i < 32; i++) {
        const float* pe = base + (size_t)(2 * i) * HWSZ;
        float4 A = __ldcs((const float4*)pe);           // even channel (stream)
        float4 O = __ldcs((const float4*)(pe + HWSZ));  // odd channel  (stream)
        float we = ws[2 * i], wo = ws[2 * i + 1];
        s.x = fmaf(A.x, we, fmaf(O.x, wo, s.x));
        s.y = fmaf(A.y, we, fmaf(O.y, wo, s.y));
        s.z = fmaf(A.z, we, fmaf(O.z, wo, s.z));
        s.w = fmaf(A.w, we, fmaf(O.w, wo, s.w));

        float2 L = hasL ? *(const float2*)(pe - 2) : make_float2(0.f, 0.f);
        float2 R = hasR ? *(const float2*)(pe + 4) : make_float2(0.f, 0.f);
        float c0 = cwt[5 * i], c1 = cwt[5 * i + 1], c2 = cwt[5 * i + 2],
              c3 = cwt[5 * i + 3], c4 = cwt[5 * i + 4];
        m0 = fmaxf(m0, L.x * c0 + L.y * c1 + A.x * c2 + A.y * c3 + A.z * c4);
        m1 = fmaxf(m1, L.y * c0 + A.x * c1 + A.y * c2 + A.z * c3 + A.w * c4);
        m2 = fmaxf(m2, A.x * c0 + A.y * c1 + A.z * c2 + A.w * c3 + R.x * c4);
        m3 = fmaxf(m3, A.y * c0 + A.z * c1 + A.w * c2 + R.x * c3 + R.y * c4);
    }
    *(float4*)(score_out + p4) = s;

    int lane = t & 31, wid = t >> 5;

    // ---- candidate append (score > CAND_T): store score, wmap, idx ----
    int p0 = s.x > CAND_T, p1 = s.y > CAND_T, p2 = s.z > CAND_T, p3 = s.w > CAND_T;
    int n = p0 + p1 + p2 + p3;
    int pre = n;
#pragma unroll
    for (int off = 1; off < 32; off <<= 1) {
        int v = __shfl_up_sync(0xffffffffu, pre, off);
        if (lane >= off) pre += v;
    }
    int total = __shfl_sync(0xffffffffu, pre, 31);
    if (total > 0) {
        int wbase = 0;
        if (lane == 31) wbase = atomicAdd(&scnt, total);
        wbase = __shfl_sync(0xffffffffu, wbase, 31);
        int o = cb * SEG + wbase + (pre - n);
        if (p0) { g_seg_val[o] = s.x; g_seg_wm[o] = m0; g_seg_idx[o] = p4;     o++; }
        if (p1) { g_seg_val[o] = s.y; g_seg_wm[o] = m1; g_seg_idx[o] = p4 + 1; o++; }
        if (p2) { g_seg_val[o] = s.z; g_seg_wm[o] = m2; g_seg_idx[o] = p4 + 2; o++; }
        if (p3) { g_seg_val[o] = s.w; g_seg_wm[o] = m3; g_seg_idx[o] = p4 + 3; }
    }

    // ---- block-exact sorted top-10 of all 1024 scores ----
    float a0 = s.x, a1 = s.y, a2 = s.z, a3 = s.w, tmp;
    if (a1 > a0) { tmp = a0; a0 = a1; a1 = tmp; }
    if (a3 > a2) { tmp = a2; a2 = a3; a3 = tmp; }
    if (a2 > a0) { tmp = a0; a0 = a2; a2 = tmp; }
    if (a3 > a1) { tmp = a1; a1 = a3; a3 = tmp; }
    if (a2 > a1) { tmp = a1; a1 = a2; a2 = tmp; }
    float st[4] = {a0, a1, a2, a3};
    warp_merge_pop<4>(st, lane, &wtop[wid * 10]);
    __syncthreads();
    if (t == 0) g_seg_cnt[cb] = scnt;
    if (wid == 0) {
        float m[10];
#pragma unroll
        for (int k = 0; k < 10; k++)
            m[k] = (lane < 8) ? wtop[lane * 10 + k] : -INFINITY;
        warp_merge_pop<10>(m, lane, &g_part[cb * 10]);
    }
    __syncthreads();

    // ---- ticket: last block of this batch -> t10 merge + sparse finalize ----
    if (t == 0) {
        __threadfence();
        s_last = (atomicAdd(&g_done[b], 1) == 63);
    }
    __syncthreads();
    if (!s_last) return;

    if (wid < 2) {
        float m[10];
        const float* src = g_part + (b * 64 + wid * 32 + lane) * 10;
#pragma unroll
        for (int k = 0; k < 10; k++) m[k] = src[k];
        warp_merge_pop<10>(m, lane, &wlist[wid][0]);
    }
    __syncthreads();
    if (wid == 0) {
        float m[10];
#pragma unroll
        for (int k = 0; k < 10; k++)
            m[k] = (lane < 2) ? wlist[lane][k] : -INFINITY;
        float t10 = warp_merge_pop<10>(m, lane, 0);
        if (lane == 0) {
            g_thresh[b] = t10;
            s_t10 = t10;
            g_done[b] = 0;                            // replay-safe reset
            while (atomicAdd(&g_zero_done, 0) < NZBLK) __nanosleep(64);
        }
    }
    __syncthreads();
    float t10 = s_t10;

    // ---- sparse finalize: this batch's 64 candidate segments ----
    for (int sg = 0; sg < 64; sg++) {
        int seg = b * 64 + sg;
        int cnt = g_seg_cnt[seg];
        for (int i = t; i < cnt; i += 256) {
            float scv = g_seg_val[seg * SEG + i];
            float sig = 1.0f / (1.0f + expf(-scv));
            bool mk = ((scv >= t10) && (sig > 0.6f)) || (sig > 0.8f);
            if (!mk) continue;
            int pix = g_seg_idx[seg * SEG + i];
            int phw = pix & (HWSZ - 1);
            float xg = (float)(phw & 255), yg = (float)(phw >> 8);
            float cw = expf(scv) * 10.0f;
            float ch = expf(g_seg_wm[seg * SEG + i]) * 10.0f;
            float x1 = floorf(xg - cw), x2 = ceilf(xg + cw);
            if (x1 < 0.0f || x2 > 256.0f) {
                float hv = fminf(256.0f - xg, xg);
                x1 = floorf(xg - hv); x2 = ceilf(xg + hv);
            }
            float y1 = floorf(yg - ch), y2 = ceilf(yg + ch);
            if (y1 < 0.0f || y2 > 256.0f) {
                float hh = fminf(256.0f - yg, yg);
                y1 = floorf(yg - hh); y2 = ceilf(yg + hh);
            }
            float* r = out_box + (size_t)pix * 5;
            r[0] = sig; r[1] = x1; r[2] = y1; r[3] = x2; r[4] = y2;
            out_m[pix] = 1.0f;
        }
    }

    // ---- last tail resets the zero/tail tickets ----
    __syncthreads();
    if (t == 0) {
        if (atomicAdd(&g_tail_done, 1) == NB - 1) {
            g_zero_done = 0;
            g_tail_done = 0;
        }
    }
}

// ---------------------------------------------------------------------------
// Launch. Output layout: score[B*HW] | out[B*HW*5] | m[B*HW]  (all f32)
// Single-kernel graph: minimal launch overhead; ncu capture lands on k_main.
// ---------------------------------------------------------------------------
extern "C" void kernel_launch(void* const* d_in, const int* in_sizes, int n_in,
                              void* d_out, int out_size) {
    const float* color   = (const float*)d_in[1];
    const float* w_bbx   = (const float*)d_in[2];
    const float* w_width = (const float*)d_in[3];
    const float* w_score = (const float*)d_in[5];

    float* score   = (float*)d_out;
    float* out_box = score + NPIX;
    float* out_m   = out_box + (size_t)NPIX * 5;

    k_main<<<NZBLK + NCBLK, 256>>>(color, w_bbx, w_width, w_score,
                                   score, out_box, out_m);
}

// round 14
// speedup vs baseline: 1.7531x; 1.7531x over previous
#include <cuda_runtime.h>
#include <math.h>

#define HWSZ 65536
#define NB 8
#define NPIX (NB * HWSZ)
#define CAND_T 0.40f
#define NCBLK 512                 // k1 compute blocks (64 per batch)
#define SEG 1024                  // candidate segment size per compute block

__device__ float g_seg_val[NCBLK * SEG];  // per-block candidate scores
__device__ float g_seg_wm[NCBLK * SEG];   // per-block candidate wmap values
__device__ int   g_seg_idx[NCBLK * SEG];  // per-block candidate pixel index
__device__ int   g_seg_cnt[NCBLK];
__device__ float g_part[NCBLK * 10];      // per-block sorted top-10 (all scores)
__device__ int   g_done[NB];              // batch completion tickets (self-resetting)
__device__ float g_thresh[NB];            // exact 10th-largest score per batch

// ---------------------------------------------------------------------------
// Warp merge-pop: each lane holds a sorted (desc) D-list; 10 rounds of
// butterfly argmax over heads; winner pops. out10 (lane 0) gets sorted top-10.
// Returns the 10th value.
// ---------------------------------------------------------------------------
template <int D>
__device__ __forceinline__ float warp_merge_pop(float (&top)[D], int lane,
                                                float* out10) {
    float last = -INFINITY;
#pragma unroll
    for (int r = 0; r < 10; r++) {
        float v = top[0]; int vi = lane;
#pragma unroll
        for (int off = 16; off; off >>= 1) {
            float ov = __shfl_xor_sync(0xffffffffu, v, off);
            int   oi = __shfl_xor_sync(0xffffffffu, vi, off);
            if (ov > v || (ov == v && oi < vi)) { v = ov; vi = oi; }
        }
        if (lane == vi) {
#pragma unroll
            for (int k = 0; k < D - 1; k++) top[k] = top[k + 1];
            top[D - 1] = -INFINITY;
        }
        if (out10 && lane == 0) out10[r] = v;
        last = v;
    }
    return last;
}

// ---------------------------------------------------------------------------
// Kernel 1 (R11 structure — measured fastest). Blocks [0,512): score + wmap
// for 4 px/thread; candidates -> per-block segment; block-exact sorted
// top-10 -> g_part; last block per batch merges 64 lists -> g_thresh[b].
// Blocks [512,1024): zero-fill out_box|out_m.
// Color loads use streaming (__ldcs): read-once data, keep L2 for writes.
// ---------------------------------------------------------------------------
__global__ void __launch_bounds__(256, 3) k_score_wmap(
    const float* __restrict__ color, const float* __restrict__ w_bbx,
    const float* __restrict__ w_width, const float* __restrict__ w_score,
    float* __restrict__ score_out, float* __restrict__ zero_base) {
    int t = threadIdx.x;
    if (blockIdx.x >= NCBLK) {               // zero-fill path: 6144 floats/block
        float* p = zero_base + (size_t)(blockIdx.x - NCBLK) * 6144 + t * 4;
        float4 z = make_float4(0.f, 0.f, 0.f, 0.f);
#pragma unroll
        for (int q = 0; q < 6; q++) *(float4*)(p + q * 1024) = z;
        return;
    }

    __shared__ float ws[64];
    __shared__ float cwt[160];
    __shared__ float wtop[8 * 10];
    __shared__ float wlist[2][10];
    __shared__ int   scnt;
    __shared__ int   s_last;
    if (t == 0) scnt = 0;
    if (t < 64) ws[t] = w_score[t];
    if (t < 160) cwt[t] = w_bbx[2 * (t / 5)] * w_width[t];
    __syncthreads();

    int p4 = (blockIdx.x * 256 + t) * 4;
    int b  = p4 >> 16;
    int hw = p4 & (HWSZ - 1);
    int w0 = hw & 255;
    const float* base = color + ((size_t)b * 64) * HWSZ + hw;

    float4 s = make_float4(0.f, 0.f, 0.f, 0.f);
    float m0 = -INFINITY, m1 = -INFINITY, m2 = -INFINITY, m3 = -INFINITY;
    const bool hasL = (w0 != 0), hasR = (w0 != 252);

#pragma unroll 4
    for (int i = 0; i < 32; i++) {
        const float* pe = base + (size_t)(2 * i) * HWSZ;
        float4 A = __ldcs((const float4*)pe);           // even channel (stream)
        float4 O = __ldcs((const float4*)(pe + HWSZ));  // odd channel  (stream)
        float we = ws[2 * i], wo = ws[2 * i + 1];
        s.x = fmaf(A.x, we, fmaf(O.x, wo, s.x));
        s.y = fmaf(A.y, we, fmaf(O.y, wo, s.y));
        s.z = fmaf(A.z, we, fmaf(O.z, wo, s.z));
        s.w = fmaf(A.w, we, fmaf(O.w, wo, s.w));

        float2 L = hasL ? *(const float2*)(pe - 2) : make_float2(0.f, 0.f);
        float2 R = hasR ? *(const float2*)(pe + 4) : make_float2(0.f, 0.f);
        float c0 = cwt[5 * i], c1 = cwt[5 * i + 1], c2 = cwt[5 * i + 2],
              c3 = cwt[5 * i + 3], c4 = cwt[5 * i + 4];
        m0 = fmaxf(m0, L.x * c0 + L.y * c1 + A.x * c2 + A.y * c3 + A.z * c4);
        m1 = fmaxf(m1, L.y * c0 + A.x * c1 + A.y * c2 + A.z * c3 + A.w * c4);
        m2 = fmaxf(m2, A.x * c0 + A.y * c1 + A.z * c2 + A.w * c3 + R.x * c4);
        m3 = fmaxf(m3, A.y * c0 + A.z * c1 + A.w * c2 + R.x * c3 + R.y * c4);
    }
    *(float4*)(score_out + p4) = s;

    int lane = t & 31, wid = t >> 5;

    // ---- candidate append (score > CAND_T): store score, wmap, idx ----
    int p0 = s.x > CAND_T, p1 = s.y > CAND_T, p2 = s.z > CAND_T, p3 = s.w > CAND_T;
    int n = p0 + p1 + p2 + p3;
    int pre = n;
#pragma unroll
    for (int off = 1; off < 32; off <<= 1) {
        int v = __shfl_up_sync(0xffffffffu, pre, off);
        if (lane >= off) pre += v;
    }
    int total = __shfl_sync(0xffffffffu, pre, 31);
    if (total > 0) {
        int wbase = 0;
        if (lane == 31) wbase = atomicAdd(&scnt, total);
        wbase = __shfl_sync(0xffffffffu, wbase, 31);
        int o = blockIdx.x * SEG + wbase + (pre - n);
        if (p0) { g_seg_val[o] = s.x; g_seg_wm[o] = m0; g_seg_idx[o] = p4;     o++; }
        if (p1) { g_seg_val[o] = s.y; g_seg_wm[o] = m1; g_seg_idx[o] = p4 + 1; o++; }
        if (p2) { g_seg_val[o] = s.z; g_seg_wm[o] = m2; g_seg_idx[o] = p4 + 2; o++; }
        if (p3) { g_seg_val[o] = s.w; g_seg_wm[o] = m3; g_seg_idx[o] = p4 + 3; }
    }

    // ---- block-exact sorted top-10 of all 1024 scores ----
    float a0 = s.x, a1 = s.y, a2 = s.z, a3 = s.w, tmp;
    if (a1 > a0) { tmp = a0; a0 = a1; a1 = tmp; }
    if (a3 > a2) { tmp = a2; a2 = a3; a3 = tmp; }
    if (a2 > a0) { tmp = a0; a0 = a2; a2 = tmp; }
    if (a3 > a1) { tmp = a1; a1 = a3; a3 = tmp; }
    if (a2 > a1) { tmp = a1; a1 = a2; a2 = tmp; }
    float st[4] = {a0, a1, a2, a3};
    warp_merge_pop<4>(st, lane, &wtop[wid * 10]);
    __syncthreads();
    if (t == 0) g_seg_cnt[blockIdx.x] = scnt;
    if (wid == 0) {
        float m[10];
#pragma unroll
        for (int k = 0; k < 10; k++)
            m[k] = (lane < 8) ? wtop[lane * 10 + k] : -INFINITY;
        warp_merge_pop<10>(m, lane, &g_part[blockIdx.x * 10]);
    }
    __syncthreads();

    // ---- ticket: last block of this batch merges the 64 top-10 lists ----
    if (t == 0) {
        __threadfence();
        s_last = (atomicAdd(&g_done[b], 1) == 63);
    }
    __syncthreads();
    if (!s_last) return;

    if (wid < 2) {
        float m[10];
        const float* src = g_part + (b * 64 + wid * 32 + lane) * 10;
#pragma unroll
        for (int k = 0; k < 10; k++) m[k] = src[k];
        warp_merge_pop<10>(m, lane, &wlist[wid][0]);
    }
    __syncthreads();
    if (wid == 0) {
        float m[10];
#pragma unroll
        for (int k = 0; k < 10; k++)
            m[k] = (lane < 2) ? wlist[lane][k] : -INFINITY;
        float t10 = warp_merge_pop<10>(m, lane, 0);
        if (lane == 0) { g_thresh[b] = t10; g_done[b] = 0; }  // replay-safe reset
    }
}

// ---------------------------------------------------------------------------
// Kernel 2: finalize. Block i processes k1-block i's candidate segment with
// the precomputed batch threshold. Sparse box writes (out pre-zeroed).
// ---------------------------------------------------------------------------
__global__ void __launch_bounds__(256) k_finalize(
    float* __restrict__ out_box, float* __restrict__ out_m) {
    int t = threadIdx.x;
    int blk = blockIdx.x;
    int b = blk >> 6;
    float t10 = g_thresh[b];
    int cnt = g_seg_cnt[blk];
    for (int i = t; i < cnt; i += 256) {
        float scv = g_seg_val[blk * SEG + i];
        float sg  = 1.0f / (1.0f + expf(-scv));
        bool m = ((scv >= t10) && (sg > 0.6f)) || (sg > 0.8f);
        if (!m) continue;
        int pix = g_seg_idx[blk * SEG + i];
        int hw = pix & (HWSZ - 1);
        float xg = (float)(hw & 255), yg = (float)(hw >> 8);
        float cw = expf(scv) * 10.0f;
        float ch = expf(g_seg_wm[blk * SEG + i]) * 10.0f;
        float x1 = floorf(xg - cw), x2 = ceilf(xg + cw);
        if (x1 < 0.0f || x2 > 256.0f) {
            float hv = fminf(256.0f - xg, xg);
            x1 = floorf(xg - hv); x2 = ceilf(xg + hv);
        }
        float y1 = floorf(yg - ch), y2 = ceilf(yg + ch);
        if (y1 < 0.0f || y2 > 256.0f) {
            float hh = fminf(256.0f - yg, yg);
            y1 = floorf(yg - hh); y2 = ceilf(yg + hh);
        }
        float* r = out_box + (size_t)pix * 5;
        r[0] = sg; r[1] = x1; r[2] = y1; r[3] = x2; r[4] = y2;
        out_m[pix] = 1.0f;
    }
}

// ---------------------------------------------------------------------------
// Launch. Output layout: score[B*HW] | out[B*HW*5] | m[B*HW]  (all f32)
// 2-launch graph: proven-fast split structure, minimal launch overhead.
// ---------------------------------------------------------------------------
extern "C" void kernel_launch(void* const* d_in, const int* in_sizes, int n_in,
                              void* d_out, int out_size) {
    const float* color   = (const float*)d_in[1];
    const float* w_bbx   = (const float*)d_in[2];
    const float* w_width = (const float*)d_in[3];
    const float* w_score = (const float*)d_in[5];

    float* score   = (float*)d_out;
    float* out_box = score + NPIX;
    float* out_m   = out_box + (size_t)NPIX * 5;

    k_score_wmap<<<1024, 256>>>(color, w_bbx, w_width, w_score, score, out_box);
    k_finalize<<<NCBLK, 256>>>(out_box, out_m);
}